// round 16
// baseline (speedup 1.0000x reference)
#include <cuda_runtime.h>
#include <cuda_bf16.h>
#include <cuda_fp16.h>
#include <cstddef>
#include <cstdint>

// Problem constants
#define B_SZ   2
#define NSEQ   2048
#define DMODEL 1024
#define NHEAD  16
#define HDIM   64
#define MTOT   (B_SZ * NSEQ)      // 4096
#define BH     (B_SZ * NHEAD)     // 32

// ---------------------------------------------------------------------------
// Scratch (static device arrays; no allocation allowed) — all single fp16
// ---------------------------------------------------------------------------
__device__ __half g_x[MTOT * DMODEL];
__device__ __half g_W0[DMODEL * DMODEL];
__device__ __half g_W1[DMODEL * DMODEL];
__device__ __half g_W2[DMODEL * DMODEL];
__device__ __half g_W3[DMODEL * DMODEL];
__device__ __half g_A[MTOT * DMODEL];
__device__ __half g_Q[BH * NSEQ * HDIM];
__device__ __half g_K[BH * NSEQ * HDIM];
__device__ __half g_V[BH * NSEQ * HDIM];

// ---------------------------------------------------------------------------
// PTX helpers
// ---------------------------------------------------------------------------
__device__ __forceinline__ uint32_t s2u(const void* p) {
    uint32_t r;
    asm("{ .reg .u64 t; cvta.to.shared.u64 t, %1; cvt.u32.u64 %0, t; }" : "=r"(r) : "l"(p));
    return r;
}
__device__ __forceinline__ void cpa16(uint32_t dst, const void* src) {
    asm volatile("cp.async.cg.shared.global [%0], [%1], 16;" :: "r"(dst), "l"(src));
}
__device__ __forceinline__ void ldsm_x4(uint32_t* r, uint32_t addr) {
    asm volatile("ldmatrix.sync.aligned.m8n8.x4.shared.b16 {%0,%1,%2,%3}, [%4];"
                 : "=r"(r[0]), "=r"(r[1]), "=r"(r[2]), "=r"(r[3]) : "r"(addr));
}
__device__ __forceinline__ void ldsm_x4_t(uint32_t* r, uint32_t addr) {
    asm volatile("ldmatrix.sync.aligned.m8n8.x4.trans.shared.b16 {%0,%1,%2,%3}, [%4];"
                 : "=r"(r[0]), "=r"(r[1]), "=r"(r[2]), "=r"(r[3]) : "r"(addr));
}
// fp16 inputs, f32 acc
__device__ __forceinline__ void mma_hf(float* c, const uint32_t* a, const uint32_t* b) {
    asm volatile("mma.sync.aligned.m16n8k16.row.col.f32.f16.f16.f32 "
                 "{%0,%1,%2,%3}, {%4,%5,%6,%7}, {%8,%9}, {%0,%1,%2,%3};"
                 : "+f"(c[0]), "+f"(c[1]), "+f"(c[2]), "+f"(c[3])
                 : "r"(a[0]), "r"(a[1]), "r"(a[2]), "r"(a[3]), "r"(b[0]), "r"(b[1]));
}
__device__ __forceinline__ float ex2(float x) {
    float y;
    asm("ex2.approx.f32 %0, %1;" : "=f"(y) : "f"(x));
    return y;
}
__device__ __forceinline__ uint32_t ex2_h2(uint32_t x) {
    uint32_t y;
    asm("ex2.approx.f16x2 %0, %1;" : "=r"(y) : "r"(x));
    return y;
}
__device__ __forceinline__ uint32_t packh2(float x, float y) {
    __half2 t = __floats2half2_rn(x, y);
    return *reinterpret_cast<uint32_t*>(&t);
}
__device__ __forceinline__ float2 unpackh2(uint32_t p) {
    return __half22float2(*reinterpret_cast<__half2*>(&p));
}

// ---------------------------------------------------------------------------
// fp32 -> fp16 converts
// ---------------------------------------------------------------------------
__global__ void conv_f16(const float* __restrict__ in, __half* __restrict__ o, int n4)
{
    int i = blockIdx.x * blockDim.x + threadIdx.x;
    if (i >= n4) return;
    float4 v = reinterpret_cast<const float4*>(in)[i];
    uint2 h;
    h.x = packh2(v.x, v.y);
    h.y = packh2(v.z, v.w);
    reinterpret_cast<uint2*>(o)[i] = h;
}

__global__ void conv_f16_w(const float* __restrict__ w0, const float* __restrict__ w1,
                           const float* __restrict__ w2, const float* __restrict__ w3,
                           __half* __restrict__ o0, __half* __restrict__ o1,
                           __half* __restrict__ o2, __half* __restrict__ o3, int n4)
{
    int i = blockIdx.x * blockDim.x + threadIdx.x;
    if (i >= n4) return;
    const float* in; __half* o;
    switch (blockIdx.y) {
        case 0: in = w0; o = o0; break;
        case 1: in = w1; o = o1; break;
        case 2: in = w2; o = o2; break;
        default: in = w3; o = o3; break;
    }
    float4 v = reinterpret_cast<const float4*>(in)[i];
    uint2 h;
    h.x = packh2(v.x, v.y);
    h.y = packh2(v.z, v.w);
    reinterpret_cast<uint2*>(o)[i] = h;
}

// ---------------------------------------------------------------------------
// Single-fp16 HMMA GEMM (proven R14): CTA 128x128, K-chunk 32, 3-stage cp.async.
// ---------------------------------------------------------------------------
#define TM 128
#define TN 128
#define KC 32
#define CHUNKS (DMODEL / KC)       // 32
#define TILE_B  8192
#define STAGE_B (2 * TILE_B)       // 16 KB
#define GSTAGES 3
#define GEMM_DSMEM (GSTAGES * STAGE_B)   // 48 KB

__device__ __forceinline__ uint32_t swz(uint32_t row, uint32_t chunk) {
    return row * 64u + ((chunk ^ ((row >> 1) & 3u)) << 4);
}

template <int MODE>
__device__ __forceinline__ void gemm_core(
        const __half* __restrict__ A, const __half* __restrict__ B,
        const float* __restrict__ bias, float* __restrict__ C,
        __half* __restrict__ Cq, float scale, char* dsm, int m0, int n0)
{
    const uint32_t sbase = s2u(dsm);
    const int tid  = threadIdx.x;
    const int wid  = tid >> 5;
    const int lane = tid & 31;
    const int wm = (wid & 3) * 32;
    const int wn = (wid >> 2) * 64;

    float acc[2][8][4];
#pragma unroll
    for (int i = 0; i < 2; i++)
#pragma unroll
        for (int j = 0; j < 8; j++)
#pragma unroll
            for (int q = 0; q < 4; q++) acc[i][j][q] = 0.f;

    const uint32_t lrow = (uint32_t)(tid >> 1);
    const uint32_t lch  = (uint32_t)(tid & 1) * 2;

    auto load_chunk = [&](int ch, int s) {
        const uint32_t sb = sbase + (uint32_t)s * STAGE_B;
        const size_t gA = (size_t)(m0 + lrow) * DMODEL + (size_t)ch * KC + lch * 8;
        const size_t gB = (size_t)(n0 + lrow) * DMODEL + (size_t)ch * KC + lch * 8;
#pragma unroll
        for (int c = 0; c < 2; c++) {
            uint32_t so = swz(lrow, lch + c);
            cpa16(sb +          so, A + gA + c * 8);
            cpa16(sb + TILE_B + so, B + gB + c * 8);
        }
        asm volatile("cp.async.commit_group;" ::: "memory");
    };

    load_chunk(0, 0);
    load_chunk(1, 1);

    int stage = 0;
    for (int ch = 0; ch < CHUNKS; ++ch) {
        if (ch + 1 < CHUNKS) { asm volatile("cp.async.wait_group 1;" ::: "memory"); }
        else                 { asm volatile("cp.async.wait_group 0;" ::: "memory"); }
        __syncthreads();
        if (ch + 2 < CHUNKS) {
            int ps = stage + 2; if (ps >= GSTAGES) ps -= GSTAGES;
            load_chunk(ch + 2, ps);
        }

        const uint32_t sb = sbase + (uint32_t)stage * STAGE_B;
#pragma unroll
        for (int kstep = 0; kstep < 2; kstep++) {
            const uint32_t kc = (uint32_t)kstep * 2;
            uint32_t a_f[2][4];
#pragma unroll
            for (int mf = 0; mf < 2; mf++) {
                uint32_t row = (uint32_t)(wm + mf * 16 + (lane & 15));
                uint32_t chn = kc + (uint32_t)(lane >> 4);
                ldsm_x4(a_f[mf], sb + swz(row, chn));
            }
#pragma unroll
            for (int nf2 = 0; nf2 < 4; nf2++) {
                uint32_t row = (uint32_t)(wn + nf2 * 16 + 8 * (lane >> 4) + (lane & 7));
                uint32_t chn = kc + (uint32_t)((lane >> 3) & 1);
                uint32_t th[4];
                ldsm_x4(th, sb + TILE_B + swz(row, chn));
#pragma unroll
                for (int mf = 0; mf < 2; mf++) {
                    mma_hf(acc[mf][2 * nf2],     a_f[mf], th);
                    mma_hf(acc[mf][2 * nf2 + 1], a_f[mf], th + 2);
                }
            }
        }
        if (++stage >= GSTAGES) stage = 0;
    }
    __syncthreads();

#pragma unroll
    for (int mf = 0; mf < 2; mf++) {
        const int rbase = m0 + wm + mf * 16 + (lane >> 2);
#pragma unroll
        for (int nf = 0; nf < 8; nf++) {
            const int n = n0 + wn + nf * 8 + (lane & 3) * 2;
            const float b0 = bias[n], b1 = bias[n + 1];
#pragma unroll
            for (int half = 0; half < 2; half++) {
                const int m = rbase + half * 8;
                float v0 = (acc[mf][nf][2 * half] + b0) * scale;
                float v1 = (acc[mf][nf][2 * half + 1] + b1) * scale;
                if (MODE == 0) {
                    *reinterpret_cast<float2*>(C + (size_t)m * DMODEL + n) =
                        make_float2(v0, v1);
                } else {
                    int h = n >> 6, hd = n & 63;
                    int b  = m >> 11, ns = m & 2047;
                    size_t idx = (((size_t)(b * NHEAD + h) * NSEQ) + ns) * HDIM + hd;
                    *reinterpret_cast<uint32_t*>(Cq + idx) = packh2(v0, v1);
                }
            }
        }
    }
}

// Q pre-scale folds 1/sqrt(HDIM) AND log2(e)
#define QSCALE 0.18033688011112042f

__global__ void __launch_bounds__(256, 2)
gemm_qkv(const __half* __restrict__ x,
         const __half* __restrict__ w0, const __half* __restrict__ w1,
         const __half* __restrict__ w2,
         const float* __restrict__ bq, const float* __restrict__ bk,
         const float* __restrict__ bv,
         __half* __restrict__ q, __half* __restrict__ k, __half* __restrict__ v)
{
    extern __shared__ char dsm[];
    const int m0 = blockIdx.y * TM;
    const int n0 = blockIdx.x * TN;
    const __half* W; const float* bias;
    __half* Cq; float scale;
    switch (blockIdx.z) {
        case 0:  W = w0; bias = bq; Cq = q; scale = QSCALE; break;
        case 1:  W = w1; bias = bk; Cq = k; scale = 1.0f;   break;
        default: W = w2; bias = bv; Cq = v; scale = 1.0f;   break;
    }
    gemm_core<1>(x, W, bias, nullptr, Cq, scale, dsm, m0, n0);
}

__global__ void __launch_bounds__(256, 2)
gemm_out(const __half* __restrict__ A, const __half* __restrict__ W,
         const float* __restrict__ bias, float* __restrict__ C)
{
    extern __shared__ char dsm[];
    gemm_core<0>(A, W, bias, C, nullptr, 1.0f, dsm,
                 blockIdx.y * TM, blockIdx.x * TN);
}

// ---------------------------------------------------------------------------
// Flash attention, 4 warps x 32 q-rows (halves per-SM ldsm traffic vs 8x16).
// fp16 operands, fp32 accum, fp16x2 exp. Q 16K + 2 x 16K stages = 48 KB.
// ---------------------------------------------------------------------------
#define FBR 128
#define FBC 64
#define FKT (NSEQ / FBC)          // 32
#define FQ 0
#define FSTG0 16384
#define FSTG_B 16384
#define FLASH_DSMEM (16384 + 2 * FSTG_B)   // 48 KB

__device__ __forceinline__ uint32_t swz8(uint32_t row, uint32_t chunk) {
    return row * 128u + ((chunk ^ (row & 7u)) << 4);
}

__global__ void __launch_bounds__(128, 2)
flash_mma(const __half* __restrict__ Q, const __half* __restrict__ K,
          const __half* __restrict__ V, __half* __restrict__ Ao)
{
    extern __shared__ char fsm[];
    const uint32_t sbase = s2u(fsm);

    const int tid  = threadIdx.x;
    const int wid  = tid >> 5;
    const int lane = tid & 31;
    const int bh   = blockIdx.y;
    const int q0   = blockIdx.x * FBR;
    const int wq   = wid * 32;            // warp q-row base (32 rows/warp)

    const size_t hb = (size_t)bh * NSEQ * HDIM;
    const __half* Qb = Q + hb;
    const __half* Kb = K + hb;
    const __half* Vb = V + hb;

    // Q tile load: 128 rows x 128B, 128 threads -> 8 chunks/thread
    {
        const size_t g = (size_t)(q0 + tid) * HDIM;
#pragma unroll
        for (int c = 0; c < 8; c++)
            cpa16(sbase + FQ + swz8((uint32_t)tid, c), Qb + g + c * 8);
    }
    auto load_kv = [&](int kt, int s) {
        const uint32_t sb = sbase + FSTG0 + (uint32_t)s * FSTG_B;
        const uint32_t row = (uint32_t)(tid >> 1);
        const uint32_t cc  = (uint32_t)(tid & 1) * 4;
        const size_t g = (size_t)(kt * FBC + row) * HDIM + cc * 8;
#pragma unroll
        for (int j = 0; j < 4; j++) {
            uint32_t sw = swz8(row, cc + j);
            cpa16(sb +        sw, Kb + g + j * 8);
            cpa16(sb + 8192u + sw, Vb + g + j * 8);
        }
        asm volatile("cp.async.commit_group;" ::: "memory");
    };
    load_kv(0, 0);

    float o[2][8][4];
#pragma unroll
    for (int mf = 0; mf < 2; mf++)
#pragma unroll
        for (int j = 0; j < 8; j++)
#pragma unroll
            for (int q = 0; q < 4; q++) o[mf][j][q] = 0.f;
    float m_s[2][2] = {{-1e30f, -1e30f}, {-1e30f, -1e30f}};
    float l_s[2][2] = {{0.f, 0.f}, {0.f, 0.f}};

    const uint32_t la15 = (uint32_t)(lane & 15);
    const uint32_t la7  = (uint32_t)(lane & 7);
    const uint32_t lb8  = 8u * (uint32_t)(lane >> 4);
    const uint32_t lbc  = (uint32_t)((lane >> 3) & 1);
    const uint32_t lac  = (uint32_t)(lane >> 4);

    for (int kt = 0; kt < FKT; kt++) {
        asm volatile("cp.async.wait_group 0;" ::: "memory");
        __syncthreads();
        if (kt + 1 < FKT) load_kv(kt + 1, (kt + 1) & 1);

        const uint32_t sb = sbase + FSTG0 + (uint32_t)(kt & 1) * FSTG_B;
        float acc[2][8][4];
#pragma unroll
        for (int mf = 0; mf < 2; mf++)
#pragma unroll
            for (int j = 0; j < 8; j++)
#pragma unroll
                for (int q = 0; q < 4; q++) acc[mf][j][q] = 0.f;

        // ---- S = Q K^T : 64 MMAs/warp (K frags amortized over 2 mf)
#pragma unroll
        for (int kf = 0; kf < 4; kf++) {
            uint32_t aQ[2][4];
#pragma unroll
            for (int mf = 0; mf < 2; mf++)
                ldsm_x4(aQ[mf], sbase + FQ +
                        swz8((uint32_t)(wq + mf * 16) + la15, 2u * kf + lac));
#pragma unroll
            for (int np = 0; np < 4; np++) {
                uint32_t kh[4];
                ldsm_x4(kh, sb + swz8((uint32_t)(np * 16) + la7 + lb8, 2u * kf + lbc));
#pragma unroll
                for (int mf = 0; mf < 2; mf++) {
                    mma_hf(acc[mf][2 * np],     aQ[mf], kh);
                    mma_hf(acc[mf][2 * np + 1], aQ[mf], kh + 2);
                }
            }
        }

        // ---- online softmax per (mf, half)
        float mn[2][2], al[2][2];
#pragma unroll
        for (int mf = 0; mf < 2; mf++) {
            float mx0 = -1e30f, mx1 = -1e30f;
#pragma unroll
            for (int nf = 0; nf < 8; nf++) {
                mx0 = fmaxf(mx0, fmaxf(acc[mf][nf][0], acc[mf][nf][1]));
                mx1 = fmaxf(mx1, fmaxf(acc[mf][nf][2], acc[mf][nf][3]));
            }
            mx0 = fmaxf(mx0, __shfl_xor_sync(0xffffffffu, mx0, 1));
            mx0 = fmaxf(mx0, __shfl_xor_sync(0xffffffffu, mx0, 2));
            mx1 = fmaxf(mx1, __shfl_xor_sync(0xffffffffu, mx1, 1));
            mx1 = fmaxf(mx1, __shfl_xor_sync(0xffffffffu, mx1, 2));
            mn[mf][0] = fmaxf(m_s[mf][0], mx0);
            mn[mf][1] = fmaxf(m_s[mf][1], mx1);
            al[mf][0] = ex2(m_s[mf][0] - mn[mf][0]);
            al[mf][1] = ex2(m_s[mf][1] - mn[mf][1]);
            m_s[mf][0] = mn[mf][0];
            m_s[mf][1] = mn[mf][1];
        }

        // ---- P frags via fp16x2 exp + fp32 row sums
        uint32_t pP[2][4][4];
        float sum[2][2] = {{0.f, 0.f}, {0.f, 0.f}};
#pragma unroll
        for (int mf = 0; mf < 2; mf++)
#pragma unroll
            for (int kf = 0; kf < 4; kf++) {
                pP[mf][kf][0] = ex2_h2(packh2(acc[mf][2 * kf][0] - mn[mf][0],
                                              acc[mf][2 * kf][1] - mn[mf][0]));
                pP[mf][kf][1] = ex2_h2(packh2(acc[mf][2 * kf][2] - mn[mf][1],
                                              acc[mf][2 * kf][3] - mn[mf][1]));
                pP[mf][kf][2] = ex2_h2(packh2(acc[mf][2 * kf + 1][0] - mn[mf][0],
                                              acc[mf][2 * kf + 1][1] - mn[mf][0]));
                pP[mf][kf][3] = ex2_h2(packh2(acc[mf][2 * kf + 1][2] - mn[mf][1],
                                              acc[mf][2 * kf + 1][3] - mn[mf][1]));
                float2 f0 = unpackh2(pP[mf][kf][0]);
                float2 f1 = unpackh2(pP[mf][kf][1]);
                float2 f2 = unpackh2(pP[mf][kf][2]);
                float2 f3 = unpackh2(pP[mf][kf][3]);
                sum[mf][0] += (f0.x + f0.y) + (f2.x + f2.y);
                sum[mf][1] += (f1.x + f1.y) + (f3.x + f3.y);
            }
#pragma unroll
        for (int mf = 0; mf < 2; mf++)
#pragma unroll
            for (int h = 0; h < 2; h++) {
                float s = sum[mf][h];
                s += __shfl_xor_sync(0xffffffffu, s, 1);
                s += __shfl_xor_sync(0xffffffffu, s, 2);
                l_s[mf][h] = l_s[mf][h] * al[mf][h] + s;
            }
#pragma unroll
        for (int mf = 0; mf < 2; mf++)
#pragma unroll
            for (int nf = 0; nf < 8; nf++) {
                o[mf][nf][0] *= al[mf][0]; o[mf][nf][1] *= al[mf][0];
                o[mf][nf][2] *= al[mf][1]; o[mf][nf][3] *= al[mf][1];
            }

        // ---- O += P V : 64 MMAs/warp (V frags amortized over 2 mf)
#pragma unroll
        for (int kf = 0; kf < 4; kf++) {
#pragma unroll
            for (int dp = 0; dp < 4; dp++) {
                uint32_t vh[4];
                ldsm_x4_t(vh, sb + 8192u +
                              swz8((uint32_t)(kf * 16) + la15, 2u * dp + lac));
#pragma unroll
                for (int mf = 0; mf < 2; mf++) {
                    mma_hf(o[mf][2 * dp],     pP[mf][kf], vh);
                    mma_hf(o[mf][2 * dp + 1], pP[mf][kf], vh + 2);
                }
            }
        }
    }

    // ---- normalize + write single fp16 A in [B,N,D]
    const int bb = bh >> 4;
    const int h  = bh & 15;
#pragma unroll
    for (int mf = 0; mf < 2; mf++) {
        const float inv0 = 1.f / l_s[mf][0], inv1 = 1.f / l_s[mf][1];
        const int qlo = q0 + wq + mf * 16 + (lane >> 2);
#pragma unroll
        for (int nf = 0; nf < 8; nf++) {
            const int gcol = h * HDIM + nf * 8 + (lane & 3) * 2;
            size_t i0 = ((size_t)(bb * NSEQ + qlo)) * DMODEL + gcol;
            *reinterpret_cast<uint32_t*>(Ao + i0) =
                packh2(o[mf][nf][0] * inv0, o[mf][nf][1] * inv0);
            size_t i1 = ((size_t)(bb * NSEQ + qlo + 8)) * DMODEL + gcol;
            *reinterpret_cast<uint32_t*>(Ao + i1) =
                packh2(o[mf][nf][2] * inv1, o[mf][nf][3] * inv1);
        }
    }
}

// ---------------------------------------------------------------------------
// Launch
// ---------------------------------------------------------------------------
extern "C" void kernel_launch(void* const* d_in, const int* in_sizes, int n_in,
                              void* d_out, int out_size)
{
    const float* x  = (const float*)d_in[0];
    const float* Wq = (const float*)d_in[1];
    const float* bq = (const float*)d_in[2];
    const float* Wk = (const float*)d_in[3];
    const float* bk = (const float*)d_in[4];
    const float* Wv = (const float*)d_in[5];
    const float* bv = (const float*)d_in[6];
    const float* Wo = (const float*)d_in[7];
    const float* bo = (const float*)d_in[8];
    float* out = (float*)d_out;

    __half *xp, *w0, *w1, *w2, *w3, *ap, *qp, *kp, *vp;
    cudaGetSymbolAddress((void**)&xp, g_x);
    cudaGetSymbolAddress((void**)&w0, g_W0);
    cudaGetSymbolAddress((void**)&w1, g_W1);
    cudaGetSymbolAddress((void**)&w2, g_W2);
    cudaGetSymbolAddress((void**)&w3, g_W3);
    cudaGetSymbolAddress((void**)&ap, g_A);
    cudaGetSymbolAddress((void**)&qp, g_Q);
    cudaGetSymbolAddress((void**)&kp, g_K);
    cudaGetSymbolAddress((void**)&vp, g_V);

    cudaFuncSetAttribute(gemm_qkv, cudaFuncAttributeMaxDynamicSharedMemorySize, GEMM_DSMEM);
    cudaFuncSetAttribute(gemm_out, cudaFuncAttributeMaxDynamicSharedMemorySize, GEMM_DSMEM);
    cudaFuncSetAttribute(flash_mma, cudaFuncAttributeMaxDynamicSharedMemorySize, FLASH_DSMEM);

    conv_f16<<<MTOT * DMODEL / 4 / 256, 256>>>(x, xp, MTOT * DMODEL / 4);
    dim3 wgrid(DMODEL * DMODEL / 4 / 256, 4);
    conv_f16_w<<<wgrid, 256>>>(Wq, Wk, Wv, Wo, w0, w1, w2, w3, DMODEL * DMODEL / 4);

    dim3 qgrid(DMODEL / TN, MTOT / TM, 3);   // (8, 32, 3)
    gemm_qkv<<<qgrid, 256, GEMM_DSMEM>>>(xp, w0, w1, w2, bq, bk, bv, qp, kp, vp);

    dim3 agrid(NSEQ / FBR, BH);              // (16, 32)
    flash_mma<<<agrid, 128, FLASH_DSMEM>>>(qp, kp, vp, ap);

    dim3 ogrid(DMODEL / TN, MTOT / TM);      // (8, 32)
    gemm_out<<<ogrid, 256, GEMM_DSMEM>>>(ap, w3, bo, out);
}

// round 17
// speedup vs baseline: 1.5872x; 1.5872x over previous
#include <cuda_runtime.h>
#include <cuda_bf16.h>
#include <cuda_fp16.h>
#include <cstddef>
#include <cstdint>

// Problem constants
#define B_SZ   2
#define NSEQ   2048
#define DMODEL 1024
#define NHEAD  16
#define HDIM   64
#define MTOT   (B_SZ * NSEQ)      // 4096
#define BH     (B_SZ * NHEAD)     // 32

// ---------------------------------------------------------------------------
// Scratch (static device arrays; no allocation allowed) — all single fp16
// ---------------------------------------------------------------------------
__device__ __half g_x[MTOT * DMODEL];
__device__ __half g_W0[DMODEL * DMODEL];
__device__ __half g_W1[DMODEL * DMODEL];
__device__ __half g_W2[DMODEL * DMODEL];
__device__ __half g_W3[DMODEL * DMODEL];
__device__ __half g_A[MTOT * DMODEL];
__device__ __half g_Q[BH * NSEQ * HDIM];
__device__ __half g_K[BH * NSEQ * HDIM];
__device__ __half g_V[BH * NSEQ * HDIM];

// ---------------------------------------------------------------------------
// PTX helpers
// ---------------------------------------------------------------------------
__device__ __forceinline__ uint32_t s2u(const void* p) {
    uint32_t r;
    asm("{ .reg .u64 t; cvta.to.shared.u64 t, %1; cvt.u32.u64 %0, t; }" : "=r"(r) : "l"(p));
    return r;
}
__device__ __forceinline__ void cpa16(uint32_t dst, const void* src) {
    asm volatile("cp.async.cg.shared.global [%0], [%1], 16;" :: "r"(dst), "l"(src));
}
__device__ __forceinline__ void ldsm_x4(uint32_t* r, uint32_t addr) {
    asm volatile("ldmatrix.sync.aligned.m8n8.x4.shared.b16 {%0,%1,%2,%3}, [%4];"
                 : "=r"(r[0]), "=r"(r[1]), "=r"(r[2]), "=r"(r[3]) : "r"(addr));
}
__device__ __forceinline__ void ldsm_x4_t(uint32_t* r, uint32_t addr) {
    asm volatile("ldmatrix.sync.aligned.m8n8.x4.trans.shared.b16 {%0,%1,%2,%3}, [%4];"
                 : "=r"(r[0]), "=r"(r[1]), "=r"(r[2]), "=r"(r[3]) : "r"(addr));
}
// fp16 inputs, f32 acc
__device__ __forceinline__ void mma_hf(float* c, const uint32_t* a, const uint32_t* b) {
    asm volatile("mma.sync.aligned.m16n8k16.row.col.f32.f16.f16.f32 "
                 "{%0,%1,%2,%3}, {%4,%5,%6,%7}, {%8,%9}, {%0,%1,%2,%3};"
                 : "+f"(c[0]), "+f"(c[1]), "+f"(c[2]), "+f"(c[3])
                 : "r"(a[0]), "r"(a[1]), "r"(a[2]), "r"(a[3]), "r"(b[0]), "r"(b[1]));
}
__device__ __forceinline__ float ex2(float x) {
    float y;
    asm("ex2.approx.f32 %0, %1;" : "=f"(y) : "f"(x));
    return y;
}
__device__ __forceinline__ uint32_t ex2_h2(uint32_t x) {
    uint32_t y;
    asm("ex2.approx.f16x2 %0, %1;" : "=r"(y) : "r"(x));
    return y;
}
__device__ __forceinline__ uint32_t packh2(float x, float y) {
    __half2 t = __floats2half2_rn(x, y);
    return *reinterpret_cast<uint32_t*>(&t);
}
__device__ __forceinline__ float2 unpackh2(uint32_t p) {
    return __half22float2(*reinterpret_cast<__half2*>(&p));
}

// ---------------------------------------------------------------------------
// fp32 -> fp16 converts
// ---------------------------------------------------------------------------
__global__ void conv_f16(const float* __restrict__ in, __half* __restrict__ o, int n4)
{
    int i = blockIdx.x * blockDim.x + threadIdx.x;
    if (i >= n4) return;
    float4 v = reinterpret_cast<const float4*>(in)[i];
    uint2 h;
    h.x = packh2(v.x, v.y);
    h.y = packh2(v.z, v.w);
    reinterpret_cast<uint2*>(o)[i] = h;
}

__global__ void conv_f16_w(const float* __restrict__ w0, const float* __restrict__ w1,
                           const float* __restrict__ w2, const float* __restrict__ w3,
                           __half* __restrict__ o0, __half* __restrict__ o1,
                           __half* __restrict__ o2, __half* __restrict__ o3, int n4)
{
    int i = blockIdx.x * blockDim.x + threadIdx.x;
    if (i >= n4) return;
    const float* in; __half* o;
    switch (blockIdx.y) {
        case 0: in = w0; o = o0; break;
        case 1: in = w1; o = o1; break;
        case 2: in = w2; o = o2; break;
        default: in = w3; o = o3; break;
    }
    float4 v = reinterpret_cast<const float4*>(in)[i];
    uint2 h;
    h.x = packh2(v.x, v.y);
    h.y = packh2(v.z, v.w);
    reinterpret_cast<uint2*>(o)[i] = h;
}

// ---------------------------------------------------------------------------
// Single-fp16 HMMA GEMM: CTA 128x128, K-chunk 32, 4-stage cp.async pipeline
// (prefetch distance 3, wait_group 2).
// ---------------------------------------------------------------------------
#define TM 128
#define TN 128
#define KC 32
#define CHUNKS (DMODEL / KC)       // 32
#define TILE_B  8192
#define STAGE_B (2 * TILE_B)       // 16 KB
#define GSTAGES 4
#define GEMM_DSMEM (GSTAGES * STAGE_B)   // 64 KB

__device__ __forceinline__ uint32_t swz(uint32_t row, uint32_t chunk) {
    return row * 64u + ((chunk ^ ((row >> 1) & 3u)) << 4);
}

template <int MODE>
__device__ __forceinline__ void gemm_core(
        const __half* __restrict__ A, const __half* __restrict__ B,
        const float* __restrict__ bias, float* __restrict__ C,
        __half* __restrict__ Cq, float scale, char* dsm, int m0, int n0)
{
    const uint32_t sbase = s2u(dsm);
    const int tid  = threadIdx.x;
    const int wid  = tid >> 5;
    const int lane = tid & 31;
    const int wm = (wid & 3) * 32;
    const int wn = (wid >> 2) * 64;

    float acc[2][8][4];
#pragma unroll
    for (int i = 0; i < 2; i++)
#pragma unroll
        for (int j = 0; j < 8; j++)
#pragma unroll
            for (int q = 0; q < 4; q++) acc[i][j][q] = 0.f;

    const uint32_t lrow = (uint32_t)(tid >> 1);
    const uint32_t lch  = (uint32_t)(tid & 1) * 2;

    auto load_chunk = [&](int ch, int s) {
        const uint32_t sb = sbase + (uint32_t)s * STAGE_B;
        const size_t gA = (size_t)(m0 + lrow) * DMODEL + (size_t)ch * KC + lch * 8;
        const size_t gB = (size_t)(n0 + lrow) * DMODEL + (size_t)ch * KC + lch * 8;
#pragma unroll
        for (int c = 0; c < 2; c++) {
            uint32_t so = swz(lrow, lch + c);
            cpa16(sb +          so, A + gA + c * 8);
            cpa16(sb + TILE_B + so, B + gB + c * 8);
        }
        asm volatile("cp.async.commit_group;" ::: "memory");
    };

    load_chunk(0, 0);
    load_chunk(1, 1);
    load_chunk(2, 2);

    for (int ch = 0; ch < CHUNKS; ++ch) {
        // Chunk ch must be complete: allow (loaded_through - ch - 1) groups
        if (ch + 2 < CHUNKS)      { asm volatile("cp.async.wait_group 2;" ::: "memory"); }
        else if (ch + 1 < CHUNKS) { asm volatile("cp.async.wait_group 1;" ::: "memory"); }
        else                      { asm volatile("cp.async.wait_group 0;" ::: "memory"); }
        __syncthreads();
        // Prefetch ch+3 into slot (ch+3)&3 = (ch-1)&3, consumed in iter ch-1,
        // protected by this iteration's barrier.
        if (ch + 3 < CHUNKS) load_chunk(ch + 3, (ch + 3) & 3);

        const uint32_t sb = sbase + (uint32_t)(ch & 3) * STAGE_B;
#pragma unroll
        for (int kstep = 0; kstep < 2; kstep++) {
            const uint32_t kc = (uint32_t)kstep * 2;
            uint32_t a_f[2][4];
#pragma unroll
            for (int mf = 0; mf < 2; mf++) {
                uint32_t row = (uint32_t)(wm + mf * 16 + (lane & 15));
                uint32_t chn = kc + (uint32_t)(lane >> 4);
                ldsm_x4(a_f[mf], sb + swz(row, chn));
            }
#pragma unroll
            for (int nf2 = 0; nf2 < 4; nf2++) {
                uint32_t row = (uint32_t)(wn + nf2 * 16 + 8 * (lane >> 4) + (lane & 7));
                uint32_t chn = kc + (uint32_t)((lane >> 3) & 1);
                uint32_t th[4];
                ldsm_x4(th, sb + TILE_B + swz(row, chn));
#pragma unroll
                for (int mf = 0; mf < 2; mf++) {
                    mma_hf(acc[mf][2 * nf2],     a_f[mf], th);
                    mma_hf(acc[mf][2 * nf2 + 1], a_f[mf], th + 2);
                }
            }
        }
    }
    __syncthreads();

#pragma unroll
    for (int mf = 0; mf < 2; mf++) {
        const int rbase = m0 + wm + mf * 16 + (lane >> 2);
#pragma unroll
        for (int nf = 0; nf < 8; nf++) {
            const int n = n0 + wn + nf * 8 + (lane & 3) * 2;
            const float b0 = bias[n], b1 = bias[n + 1];
#pragma unroll
            for (int half = 0; half < 2; half++) {
                const int m = rbase + half * 8;
                float v0 = (acc[mf][nf][2 * half] + b0) * scale;
                float v1 = (acc[mf][nf][2 * half + 1] + b1) * scale;
                if (MODE == 0) {
                    *reinterpret_cast<float2*>(C + (size_t)m * DMODEL + n) =
                        make_float2(v0, v1);
                } else {
                    int h = n >> 6, hd = n & 63;
                    int b  = m >> 11, ns = m & 2047;
                    size_t idx = (((size_t)(b * NHEAD + h) * NSEQ) + ns) * HDIM + hd;
                    *reinterpret_cast<uint32_t*>(Cq + idx) = packh2(v0, v1);
                }
            }
        }
    }
}

// Q pre-scale folds 1/sqrt(HDIM) AND log2(e)
#define QSCALE 0.18033688011112042f

__global__ void __launch_bounds__(256, 2)
gemm_qkv(const __half* __restrict__ x,
         const __half* __restrict__ w0, const __half* __restrict__ w1,
         const __half* __restrict__ w2,
         const float* __restrict__ bq, const float* __restrict__ bk,
         const float* __restrict__ bv,
         __half* __restrict__ q, __half* __restrict__ k, __half* __restrict__ v)
{
    extern __shared__ char dsm[];
    const int m0 = blockIdx.y * TM;
    const int n0 = blockIdx.x * TN;
    const __half* W; const float* bias;
    __half* Cq; float scale;
    switch (blockIdx.z) {
        case 0:  W = w0; bias = bq; Cq = q; scale = QSCALE; break;
        case 1:  W = w1; bias = bk; Cq = k; scale = 1.0f;   break;
        default: W = w2; bias = bv; Cq = v; scale = 1.0f;   break;
    }
    gemm_core<1>(x, W, bias, nullptr, Cq, scale, dsm, m0, n0);
}

__global__ void __launch_bounds__(256, 2)
gemm_out(const __half* __restrict__ A, const __half* __restrict__ W,
         const float* __restrict__ bias, float* __restrict__ C)
{
    extern __shared__ char dsm[];
    gemm_core<0>(A, W, bias, C, nullptr, 1.0f, dsm,
                 blockIdx.y * TM, blockIdx.x * TN);
}

// ---------------------------------------------------------------------------
// Flash attention (exact R15 kernel): 8 warps x 16 q-rows, fp16 operands,
// fp32 accum, fp16x2 exp. Q 16K + 2 x 16K stages = 48 KB, occ 2.
// ---------------------------------------------------------------------------
#define FBR 128
#define FBC 64
#define FKT (NSEQ / FBC)          // 32
#define FQ 0
#define FSTG0 16384
#define FSTG_B 16384
#define FLASH_DSMEM (16384 + 2 * FSTG_B)   // 48 KB

__device__ __forceinline__ uint32_t swz8(uint32_t row, uint32_t chunk) {
    return row * 128u + ((chunk ^ (row & 7u)) << 4);
}

__global__ void __launch_bounds__(256, 2)
flash_mma(const __half* __restrict__ Q, const __half* __restrict__ K,
          const __half* __restrict__ V, __half* __restrict__ Ao)
{
    extern __shared__ char fsm[];
    const uint32_t sbase = s2u(fsm);

    const int tid  = threadIdx.x;
    const int wid  = tid >> 5;
    const int lane = tid & 31;
    const int bh   = blockIdx.y;
    const int q0   = blockIdx.x * FBR;

    const size_t hb = (size_t)bh * NSEQ * HDIM;
    const __half* Qb = Q + hb;
    const __half* Kb = K + hb;
    const __half* Vb = V + hb;

    {
        const uint32_t row = (uint32_t)(tid >> 1);
        const uint32_t c0  = (uint32_t)(tid & 1) * 4;
        const size_t g = (size_t)(q0 + row) * HDIM + c0 * 8;
#pragma unroll
        for (int c = 0; c < 4; c++)
            cpa16(sbase + FQ + swz8(row, c0 + c), Qb + g + c * 8);
    }
    auto load_kv = [&](int kt, int s) {
        const uint32_t sb = sbase + FSTG0 + (uint32_t)s * FSTG_B;
        const uint32_t row = (uint32_t)(tid >> 2);
        const uint32_t cc  = (uint32_t)(tid & 3) * 2;
        const size_t g = (size_t)(kt * FBC + row) * HDIM + cc * 8;
#pragma unroll
        for (int j = 0; j < 2; j++) {
            uint32_t sw = swz8(row, cc + j);
            cpa16(sb +        sw, Kb + g + j * 8);
            cpa16(sb + 8192u + sw, Vb + g + j * 8);
        }
        asm volatile("cp.async.commit_group;" ::: "memory");
    };
    load_kv(0, 0);

    float o[8][4];
#pragma unroll
    for (int j = 0; j < 8; j++)
#pragma unroll
        for (int q = 0; q < 4; q++) o[j][q] = 0.f;
    float m0s = -1e30f, m1s = -1e30f, l0s = 0.f, l1s = 0.f;

    const uint32_t la15 = (uint32_t)(lane & 15);
    const uint32_t la7  = (uint32_t)(lane & 7);
    const uint32_t lb8  = 8u * (uint32_t)(lane >> 4);
    const uint32_t lbc  = (uint32_t)((lane >> 3) & 1);
    const uint32_t lac  = (uint32_t)(lane >> 4);

    for (int kt = 0; kt < FKT; kt++) {
        asm volatile("cp.async.wait_group 0;" ::: "memory");
        __syncthreads();
        if (kt + 1 < FKT) load_kv(kt + 1, (kt + 1) & 1);

        const uint32_t sb = sbase + FSTG0 + (uint32_t)(kt & 1) * FSTG_B;
        float acc[8][4];
#pragma unroll
        for (int j = 0; j < 8; j++)
#pragma unroll
            for (int q = 0; q < 4; q++) acc[j][q] = 0.f;

        // ---- S = Q K^T : 32 MMAs
#pragma unroll
        for (int kf = 0; kf < 4; kf++) {
            uint32_t aQ[4];
            ldsm_x4(aQ, sbase + FQ + swz8((uint32_t)(wid * 16) + la15, 2u * kf + lac));
#pragma unroll
            for (int np = 0; np < 4; np++) {
                uint32_t kh[4];
                ldsm_x4(kh, sb + swz8((uint32_t)(np * 16) + la7 + lb8, 2u * kf + lbc));
                mma_hf(acc[2 * np],     aQ, kh);
                mma_hf(acc[2 * np + 1], aQ, kh + 2);
            }
        }

        // ---- online softmax: max (fp32) -> packed fp16x2 exp -> fp32 sums
        float mx0 = -1e30f, mx1 = -1e30f;
#pragma unroll
        for (int nf = 0; nf < 8; nf++) {
            mx0 = fmaxf(mx0, fmaxf(acc[nf][0], acc[nf][1]));
            mx1 = fmaxf(mx1, fmaxf(acc[nf][2], acc[nf][3]));
        }
        mx0 = fmaxf(mx0, __shfl_xor_sync(0xffffffffu, mx0, 1));
        mx0 = fmaxf(mx0, __shfl_xor_sync(0xffffffffu, mx0, 2));
        mx1 = fmaxf(mx1, __shfl_xor_sync(0xffffffffu, mx1, 1));
        mx1 = fmaxf(mx1, __shfl_xor_sync(0xffffffffu, mx1, 2));
        float mn0 = fmaxf(m0s, mx0), mn1 = fmaxf(m1s, mx1);
        float al0 = ex2(m0s - mn0), al1 = ex2(m1s - mn1);
        m0s = mn0; m1s = mn1;

        uint32_t pP[4][4];
        float sum0 = 0.f, sum1 = 0.f;
#pragma unroll
        for (int kf = 0; kf < 4; kf++) {
            pP[kf][0] = ex2_h2(packh2(acc[2 * kf][0] - mn0,     acc[2 * kf][1] - mn0));
            pP[kf][1] = ex2_h2(packh2(acc[2 * kf][2] - mn1,     acc[2 * kf][3] - mn1));
            pP[kf][2] = ex2_h2(packh2(acc[2 * kf + 1][0] - mn0, acc[2 * kf + 1][1] - mn0));
            pP[kf][3] = ex2_h2(packh2(acc[2 * kf + 1][2] - mn1, acc[2 * kf + 1][3] - mn1));
            float2 f0 = unpackh2(pP[kf][0]);
            float2 f1 = unpackh2(pP[kf][1]);
            float2 f2 = unpackh2(pP[kf][2]);
            float2 f3 = unpackh2(pP[kf][3]);
            sum0 += (f0.x + f0.y) + (f2.x + f2.y);
            sum1 += (f1.x + f1.y) + (f3.x + f3.y);
        }
        sum0 += __shfl_xor_sync(0xffffffffu, sum0, 1);
        sum0 += __shfl_xor_sync(0xffffffffu, sum0, 2);
        sum1 += __shfl_xor_sync(0xffffffffu, sum1, 1);
        sum1 += __shfl_xor_sync(0xffffffffu, sum1, 2);
        l0s = l0s * al0 + sum0;
        l1s = l1s * al1 + sum1;
#pragma unroll
        for (int nf = 0; nf < 8; nf++) {
            o[nf][0] *= al0; o[nf][1] *= al0;
            o[nf][2] *= al1; o[nf][3] *= al1;
        }

        // ---- O += P V : 32 MMAs, pP already packed
#pragma unroll
        for (int kf = 0; kf < 4; kf++) {
#pragma unroll
            for (int dp = 0; dp < 4; dp++) {
                uint32_t vh[4];
                ldsm_x4_t(vh, sb + 8192u +
                              swz8((uint32_t)(kf * 16) + la15, 2u * dp + lac));
                mma_hf(o[2 * dp],     pP[kf], vh);
                mma_hf(o[2 * dp + 1], pP[kf], vh + 2);
            }
        }
    }

    // ---- normalize + write single fp16 A in [B,N,D]
    const int bb = bh >> 4;
    const int h  = bh & 15;
    const float inv0 = 1.f / l0s, inv1 = 1.f / l1s;
    const int qlo = q0 + wid * 16 + (lane >> 2);
#pragma unroll
    for (int nf = 0; nf < 8; nf++) {
        const int gcol = h * HDIM + nf * 8 + (lane & 3) * 2;
        size_t i0 = ((size_t)(bb * NSEQ + qlo)) * DMODEL + gcol;
        *reinterpret_cast<uint32_t*>(Ao + i0) = packh2(o[nf][0] * inv0, o[nf][1] * inv0);
        size_t i1 = ((size_t)(bb * NSEQ + qlo + 8)) * DMODEL + gcol;
        *reinterpret_cast<uint32_t*>(Ao + i1) = packh2(o[nf][2] * inv1, o[nf][3] * inv1);
    }
}

// ---------------------------------------------------------------------------
// Launch
// ---------------------------------------------------------------------------
extern "C" void kernel_launch(void* const* d_in, const int* in_sizes, int n_in,
                              void* d_out, int out_size)
{
    const float* x  = (const float*)d_in[0];
    const float* Wq = (const float*)d_in[1];
    const float* bq = (const float*)d_in[2];
    const float* Wk = (const float*)d_in[3];
    const float* bk = (const float*)d_in[4];
    const float* Wv = (const float*)d_in[5];
    const float* bv = (const float*)d_in[6];
    const float* Wo = (const float*)d_in[7];
    const float* bo = (const float*)d_in[8];
    float* out = (float*)d_out;

    __half *xp, *w0, *w1, *w2, *w3, *ap, *qp, *kp, *vp;
    cudaGetSymbolAddress((void**)&xp, g_x);
    cudaGetSymbolAddress((void**)&w0, g_W0);
    cudaGetSymbolAddress((void**)&w1, g_W1);
    cudaGetSymbolAddress((void**)&w2, g_W2);
    cudaGetSymbolAddress((void**)&w3, g_W3);
    cudaGetSymbolAddress((void**)&ap, g_A);
    cudaGetSymbolAddress((void**)&qp, g_Q);
    cudaGetSymbolAddress((void**)&kp, g_K);
    cudaGetSymbolAddress((void**)&vp, g_V);

    cudaFuncSetAttribute(gemm_qkv, cudaFuncAttributeMaxDynamicSharedMemorySize, GEMM_DSMEM);
    cudaFuncSetAttribute(gemm_out, cudaFuncAttributeMaxDynamicSharedMemorySize, GEMM_DSMEM);
    cudaFuncSetAttribute(flash_mma, cudaFuncAttributeMaxDynamicSharedMemorySize, FLASH_DSMEM);

    conv_f16<<<MTOT * DMODEL / 4 / 256, 256>>>(x, xp, MTOT * DMODEL / 4);
    dim3 wgrid(DMODEL * DMODEL / 4 / 256, 4);
    conv_f16_w<<<wgrid, 256>>>(Wq, Wk, Wv, Wo, w0, w1, w2, w3, DMODEL * DMODEL / 4);

    dim3 qgrid(DMODEL / TN, MTOT / TM, 3);   // (8, 32, 3)
    gemm_qkv<<<qgrid, 256, GEMM_DSMEM>>>(xp, w0, w1, w2, bq, bk, bv, qp, kp, vp);

    dim3 agrid(NSEQ / FBR, BH);              // (16, 32)
    flash_mma<<<agrid, 256, FLASH_DSMEM>>>(qp, kp, vp, ap);

    dim3 ogrid(DMODEL / TN, MTOT / TM);      // (8, 32)
    gemm_out<<<ogrid, 256, GEMM_DSMEM>>>(ap, w3, bo, out);
}